// round 11
// baseline (speedup 1.0000x reference)
#include <cuda_runtime.h>
#include <cstdint>

#define D     64
#define NMEM  16
#define NHOP  2
#define NREL  200
#define BMAX  4096
#define SMAX  (BMAX * NMEM)   // 65536 slots per hop
#define TM    96              // slots per GEMM tile (16 ts-groups x 6)
#define KS    6               // slots per thread
#define RPAD  68              // RsT row stride (floats)
#define CBLK  32              // histogram/scatter blocks per hop
#define YSPLIT 4              // blocks per bin

// smem layout for k_gemm (bytes)
#define ROFF   0
#define RBYTES (D * RPAD * 4)                 // 17408
#define HOFF   RBYTES
#define HROWB  256                            // 64 floats per row (skew wraps in-row)
#define HBYTES (TM * HROWB)                   // 24576
#define SOFF   (HOFF + HBYTES)
#define GEMM_SMEM (SOFF + TM * 4)             // 42368 -> 5 blocks/SM

// ---- persistent scratch (no runtime allocation allowed) ----
__device__ int   g_parthist[NHOP][CBLK][NREL];
__device__ int   g_off   [NHOP][NREL + 1];
__device__ int   g_cursor[NHOP][NREL];
__device__ int   g_slots [NHOP][SMAX];
__device__ float g_logits[NHOP][SMAX];
__device__ float g_item  [BMAX][D];
__device__ float g_y     [BMAX][D];
__device__ float g_Wt    [D * D];           // Wt[j][i] = W[i][j]

// ------------------------------------------------------------------
__device__ __forceinline__ uint32_t smem_u32(const void* p) {
    return (uint32_t)__cvta_generic_to_shared(p);
}
__device__ __forceinline__ void cp16(uint32_t dst, const void* src) {
    asm volatile("cp.async.cg.shared.global [%0], [%1], 16;\n"
                 :: "r"(dst), "l"(src));
}
__device__ __forceinline__ void cp_commit() {
    asm volatile("cp.async.commit_group;\n" ::);
}
template <int N>
__device__ __forceinline__ void cp_wait() {
    asm volatile("cp.async.wait_group %0;\n" :: "n"(N));
}

// packed f32x2 helpers
__device__ __forceinline__ unsigned long long pack2(float v) {
    unsigned long long r;
    asm("mov.b64 %0, {%1, %1};" : "=l"(r) : "f"(v));
    return r;
}
__device__ __forceinline__ void fma2(unsigned long long& d,
                                     unsigned long long a,
                                     unsigned long long b) {
    asm("fma.rn.f32x2 %0, %1, %2, %0;" : "+l"(d) : "l"(a), "l"(b));
}
__device__ __forceinline__ float hsum2(unsigned long long v) {
    float lo, hi;
    asm("mov.b64 {%0, %1}, %2;" : "=f"(lo), "=f"(hi) : "l"(v));
    return lo + hi;
}

// ------------------------------------------------------------------
// histogram + g_item init (item embeddings gathered once)
__global__ __launch_bounds__(256)
void k_count(const int* __restrict__ mem_r,
             const int* __restrict__ items,
             const float* __restrict__ entity, int B)
{
    __shared__ int hist[NREL];
    const int hop   = blockIdx.y;
    const int total = B * NMEM;
    const int chunk = (total + CBLK - 1) / CBLK;
    const int start = blockIdx.x * chunk;

    for (int i = threadIdx.x; i < NREL; i += 256) hist[i] = 0;
    __syncthreads();

    const int* src = mem_r + hop * total;
    {
        int base = start + threadIdx.x * 8;
        if (base + 8 <= start + chunk && start + chunk <= total) {
            int4 v0 = *(const int4*)(src + base);
            int4 v1 = *(const int4*)(src + base + 4);
            atomicAdd(&hist[v0.x], 1); atomicAdd(&hist[v0.y], 1);
            atomicAdd(&hist[v0.z], 1); atomicAdd(&hist[v0.w], 1);
            atomicAdd(&hist[v1.x], 1); atomicAdd(&hist[v1.y], 1);
            atomicAdd(&hist[v1.z], 1); atomicAdd(&hist[v1.w], 1);
        } else {
            for (int k = threadIdx.x * 8; k < threadIdx.x * 8 + 8; ++k)
                if (k < chunk && start + k < total)
                    atomicAdd(&hist[src[start + k]], 1);
        }
    }

    // g_item[b] = entity[items[b]]  (independent of histogram)
    {
        const int nthr = CBLK * NHOP * 256;
        int gid = (blockIdx.y * CBLK + blockIdx.x) * 256 + threadIdx.x;
        const int nvec = B * (D / 4);          // float4 count
        for (int i = gid; i < nvec; i += nthr) {
            int b = i >> 4, c = i & 15;
            ((float4*)g_item)[i] =
                ((const float4*)(entity + (size_t)items[b] * D))[c];
        }
    }
    __syncthreads();

    for (int i = threadIdx.x; i < NREL; i += 256)
        g_parthist[hop][blockIdx.x][i] = hist[i];
}

__global__ __launch_bounds__(512)
void k_scan(const float* __restrict__ W)
{
    __shared__ int cnt[NHOP][NREL];
    const int tid = threadIdx.x;
    if (tid < NHOP * NREL) {
        int hop = tid / NREL, r = tid - hop * NREL;
        int s = 0;
        #pragma unroll 8
        for (int b = 0; b < CBLK; ++b) s += g_parthist[hop][b][r];
        cnt[hop][r] = s;
        g_cursor[hop][r] = 0;
    }
    for (int idx = tid; idx < D * D; idx += 512)
        g_Wt[(idx & (D - 1)) * D + (idx >> 6)] = W[idx];
    __syncthreads();
    if (tid < NHOP) {
        int acc = 0;
        for (int r = 0; r < NREL; ++r) { g_off[tid][r] = acc; acc += cnt[tid][r]; }
        g_off[tid][NREL] = acc;
    }
}

__global__ __launch_bounds__(256)
void k_scatter(const int* __restrict__ mem_r, int B)
{
    __shared__ int hist[NREL];
    __shared__ int base_s[NREL];
    const int hop   = blockIdx.y;
    const int total = B * NMEM;
    const int chunk = (total + CBLK - 1) / CBLK;
    const int start = blockIdx.x * chunk;

    for (int i = threadIdx.x; i < NREL; i += 256) hist[i] = 0;
    __syncthreads();

    const int* src = mem_r + hop * total;
    int rr[8], lrank[8], idx0 = start + threadIdx.x * 8;
    bool vec = ((chunk & 7) == 0) && (idx0 + 8 <= start + chunk) &&
               (start + chunk <= total);
    if (vec) {
        int4 v0 = *(const int4*)(src + idx0);
        int4 v1 = *(const int4*)(src + idx0 + 4);
        rr[0]=v0.x; rr[1]=v0.y; rr[2]=v0.z; rr[3]=v0.w;
        rr[4]=v1.x; rr[5]=v1.y; rr[6]=v1.z; rr[7]=v1.w;
        #pragma unroll
        for (int t = 0; t < 8; ++t) lrank[t] = atomicAdd(&hist[rr[t]], 1);
    } else {
        #pragma unroll
        for (int t = 0; t < 8; ++t) {
            int k = threadIdx.x * 8 + t;
            rr[t] = -1;
            if (k < chunk && start + k < total) {
                rr[t]    = src[start + k];
                lrank[t] = atomicAdd(&hist[rr[t]], 1);
            }
        }
    }
    __syncthreads();

    for (int i = threadIdx.x; i < NREL; i += 256) {
        int c = hist[i];
        base_s[i] = g_off[hop][i] + (c ? atomicAdd(&g_cursor[hop][i], c) : 0);
    }
    __syncthreads();

    #pragma unroll
    for (int t = 0; t < 8; ++t)
        if (vec || rr[t] >= 0)
            g_slots[hop][base_s[rr[t]] + lrank[t]] = idx0 + t;
}

// ------------------------------------------------------------------
// Fused GEMM + logit dot for ONE hop:
//   logit[slot] = item_{b(slot)} . (R_{r} @ h_slot)
// Grid (NREL, YSPLIT). 128 threads, 6x8 packed micro-tile, then each
// thread dots its 8 dims against g_item and 8-lane shuffle-reduces.
__global__ __launch_bounds__(128, 5)
void k_gemm(const int* __restrict__ mem_h,
            const float* __restrict__ entity,
            const float* __restrict__ rel,
            int hop, int B)
{
    const int r    = blockIdx.x;
    const int base = g_off[hop][r];
    const int n    = g_off[hop][r + 1] - base;
    const int ntiles = (n + TM - 1) / TM;
    if ((int)blockIdx.y >= ntiles) return;

    extern __shared__ char smem[];
    float (*RsT)[RPAD] = (float(*)[RPAD])(smem + ROFF);
    const uint32_t hbase = smem_u32(smem + HOFF);
    int* sslot = (int*)(smem + SOFF);

    const int tid  = threadIdx.x;
    const int ts   = tid >> 3;      // 0..15
    const int ti   = tid & 7;       // 0..7

    const int* __restrict__ mh = mem_h + (size_t)hop * B * NMEM;

    bool first = true;
    for (int t = blockIdx.y; t < ntiles; t += YSPLIT) {
        if (!first) __syncthreads();   // previous compute done before overwrite

        // gather tile t into H (in-row 16B skew)
        {
            int s = t * TM + tid;
            if (tid < TM) {
                int slot = (s < n) ? g_slots[hop][base + s] : -1;
                sslot[tid] = slot;
                if (slot >= 0) {
                    const char* src = (const char*)(entity + (size_t)mh[slot] * D);
                    uint32_t rowbase = hbase + tid * HROWB;
                    const uint32_t sk = (tid & 7) * 16;
                    #pragma unroll
                    for (int c = 0; c < 16; ++c)
                        cp16(rowbase + ((sk + c * 16) & 255), src + c * 16);
                }
            }
            cp_commit();
        }

        if (first) {
            const float* __restrict__ Rp = rel + (size_t)r * (D * D);
            for (int idx = tid; idx < D * D; idx += 128) {
                int i = idx >> 6, j = idx & 63;
                RsT[j][i] = Rp[idx];
            }
            first = false;
        }

        cp_wait<0>();
        __syncthreads();

        const float4* R4 = (const float4*)(smem + ROFF);
        const float4* H4 = (const float4*)(smem + HOFF);

        unsigned long long acc2[KS][4];
        #pragma unroll
        for (int k = 0; k < KS; ++k)
            #pragma unroll
            for (int p = 0; p < 4; ++p) acc2[k][p] = 0ull;

        #pragma unroll 2
        for (int jq = 0; jq < 16; ++jq) {
            float af[KS][4];
            #pragma unroll
            for (int k = 0; k < KS; ++k) {
                float4 a = H4[(ts + 16 * k) * 16 + (((ts & 7) + jq) & 15)];
                af[k][0] = a.x; af[k][1] = a.y; af[k][2] = a.z; af[k][3] = a.w;
            }
            #pragma unroll
            for (int jj = 0; jj < 4; ++jj) {
                const ulonglong2* bp =
                    (const ulonglong2*)(R4 + (4 * jq + jj) * (RPAD / 4) + ti * 2);
                ulonglong2 t0 = bp[0], t1 = bp[1];
                unsigned long long b2[4] = {t0.x, t0.y, t1.x, t1.y};
                #pragma unroll
                for (int k = 0; k < KS; ++k) {
                    unsigned long long av2 = pack2(af[k][jj]);
                    #pragma unroll
                    for (int p = 0; p < 4; ++p)
                        fma2(acc2[k][p], av2, b2[p]);
                }
            }
        }

        // fused epilogue: logit = acc . item_b, 8-lane reduce, 1 float out
        #pragma unroll
        for (int k = 0; k < KS; ++k) {
            int slot = sslot[ts + 16 * k];
            float dot = 0.0f;
            if (slot >= 0) {
                const ulonglong2* iv =
                    (const ulonglong2*)&g_item[slot >> 4][ti * 8];
                ulonglong2 q0 = iv[0], q1 = iv[1];
                unsigned long long d2 = 0ull;
                fma2(d2, acc2[k][0], q0.x);
                fma2(d2, acc2[k][1], q0.y);
                fma2(d2, acc2[k][2], q1.x);
                fma2(d2, acc2[k][3], q1.y);
                dot = hsum2(d2);
            }
            dot += __shfl_xor_sync(0xffffffffu, dot, 1);
            dot += __shfl_xor_sync(0xffffffffu, dot, 2);
            dot += __shfl_xor_sync(0xffffffffu, dot, 4);
            if (ti == 0 && slot >= 0) g_logits[hop][slot] = dot;
        }
    }
}

// ------------------------------------------------------------------
// Per-hop epilogue: softmax, o = probs.t, y accumulate, item = Wt@(item+o);
// hop 1 also writes score. 2 batch elements per 128-thread block.
__global__ __launch_bounds__(128)
void k_upd(const int* __restrict__ mem_t,
           const float* __restrict__ entity,
           float* __restrict__ out,
           int hop, int B)
{
    const int tid  = threadIdx.x;
    const int sub  = tid >> 6;
    const int t    = tid & 63;
    const int lane = tid & 31;
    const int warp = tid >> 5;
    const int b    = blockIdx.x * 2 + sub;

    __shared__ float lgs[2][NMEM];
    __shared__ float probs[2][NMEM];
    __shared__ float vbuf[2][D];
    __shared__ float red[4];

    float item = g_item[b][t];

    if (t < NMEM) lgs[sub][t] = g_logits[hop][b * NMEM + t];
    __syncthreads();

    if (t < NMEM) {
        float mx = lgs[sub][0];
        #pragma unroll
        for (int k = 1; k < NMEM; ++k) mx = fmaxf(mx, lgs[sub][k]);
        probs[sub][t] = expf(lgs[sub][t] - mx);
    }
    __syncthreads();

    float denom = 0.0f;
    #pragma unroll
    for (int m = 0; m < NMEM; ++m) denom += probs[sub][m];

    const int* tp = mem_t + (size_t)hop * B * NMEM + b * NMEM;
    float o = 0.0f;
    #pragma unroll
    for (int m = 0; m < NMEM; ++m)
        o = fmaf(probs[sub][m], entity[(size_t)tp[m] * D + t], o);
    o /= denom;

    float y = (hop ? g_y[b][t] : 0.0f) + o;
    if (hop == 0) g_y[b][t] = y;
    vbuf[sub][t] = item + o;
    __syncthreads();

    float acc = 0.0f;
    #pragma unroll 8
    for (int j = 0; j < D; ++j)
        acc = fmaf(g_Wt[j * D + t], vbuf[sub][j], acc);

    if (hop == 0) {
        g_item[b][t] = acc;
    } else {
        float p = acc * y;
        #pragma unroll
        for (int off = 16; off > 0; off >>= 1)
            p += __shfl_xor_sync(0xffffffffu, p, off);
        if (lane == 0) red[warp] = p;
        __syncthreads();
        if (tid == 0)  out[b] = red[0] + red[1];
        if (tid == 64) out[b] = red[2] + red[3];
    }
}

// ------------------------------------------------------------------
extern "C" void kernel_launch(void* const* d_in, const int* in_sizes, int n_in,
                              void* d_out, int out_size)
{
    const int*   items  = (const int*)  d_in[0];
    const int*   mem_h  = (const int*)  d_in[1];
    const int*   mem_r  = (const int*)  d_in[2];
    const int*   mem_t  = (const int*)  d_in[3];
    const float* entity = (const float*)d_in[4];
    const float* rel    = (const float*)d_in[5];
    const float* W      = (const float*)d_in[6];
    float*       out    = (float*)d_out;

    const int B = in_sizes[0];   // 4096

    static bool attr_set = false;
    if (!attr_set) {
        cudaFuncSetAttribute(k_gemm, cudaFuncAttributeMaxDynamicSharedMemorySize,
                             GEMM_SMEM);
        attr_set = true;
    }

    k_count  <<<dim3(CBLK, NHOP), 256>>>(mem_r, items, entity, B);
    k_scan   <<<1, 512>>>(W);
    k_scatter<<<dim3(CBLK, NHOP), 256>>>(mem_r, B);
    k_gemm   <<<dim3(NREL, YSPLIT), 128, GEMM_SMEM>>>(mem_h, entity, rel, 0, B);
    k_upd    <<<B / 2, 128>>>(mem_t, entity, out, 0, B);
    k_gemm   <<<dim3(NREL, YSPLIT), 128, GEMM_SMEM>>>(mem_h, entity, rel, 1, B);
    k_upd    <<<B / 2, 128>>>(mem_t, entity, out, 1, B);
}

// round 12
// speedup vs baseline: 1.0094x; 1.0094x over previous
#include <cuda_runtime.h>
#include <cstdint>

#define D     64
#define NMEM  16
#define NHOP  2
#define NREL  200
#define BMAX  4096
#define SMAX  (BMAX * NMEM)   // 65536 slots per hop
#define TM    96              // slots per GEMM tile (16 ts-groups x 6)
#define KS    6               // slots per thread
#define CBLK  32              // histogram/scatter blocks per hop
#define YSPLIT 4              // blocks per bin

// smem layout for k_gemm (bytes): R (no pad) + H + slot ids
#define ROFF   0
#define RBYTES (D * D * 4)                    // 16384
#define HOFF   RBYTES
#define HROWB  256                            // 64 floats per row (skew wraps in-row)
#define HBYTES (TM * HROWB)                   // 24576
#define SOFF   (HOFF + HBYTES)
#define GEMM_SMEM (SOFF + TM * 4)             // 41344 -> 5 blocks/SM

// ---- persistent scratch (no runtime allocation allowed) ----
__device__ int   g_parthist[NHOP][CBLK][NREL];
__device__ int   g_off   [NHOP][NREL + 1];
__device__ int   g_cursor[NHOP][NREL];
__device__ int   g_slots [NHOP][SMAX];
__device__ float g_logits0[SMAX];           // hop-0 logits (fused in gemm)
__device__ float g_Y1    [SMAX][D];         // hop-1 Y rows
__device__ float g_item  [BMAX][D];
__device__ float g_y     [BMAX][D];
__device__ float g_Wt    [D * D];           // Wt[j][i] = W[i][j]
__device__ float g_RT    [NREL][D * D];     // RT[r][j*64+i] = R[r][i][j]

// ------------------------------------------------------------------
__device__ __forceinline__ uint32_t smem_u32(const void* p) {
    return (uint32_t)__cvta_generic_to_shared(p);
}
__device__ __forceinline__ void cp16(uint32_t dst, const void* src) {
    asm volatile("cp.async.cg.shared.global [%0], [%1], 16;\n"
                 :: "r"(dst), "l"(src));
}
__device__ __forceinline__ void cp_commit() {
    asm volatile("cp.async.commit_group;\n" ::);
}
template <int N>
__device__ __forceinline__ void cp_wait() {
    asm volatile("cp.async.wait_group %0;\n" :: "n"(N));
}

// packed f32x2 helpers
__device__ __forceinline__ unsigned long long pack2(float v) {
    unsigned long long r;
    asm("mov.b64 %0, {%1, %1};" : "=l"(r) : "f"(v));
    return r;
}
__device__ __forceinline__ void fma2(unsigned long long& d,
                                     unsigned long long a,
                                     unsigned long long b) {
    asm("fma.rn.f32x2 %0, %1, %2, %0;" : "+l"(d) : "l"(a), "l"(b));
}
__device__ __forceinline__ float hsum2(unsigned long long v) {
    float lo, hi;
    asm("mov.b64 {%0, %1}, %2;" : "=f"(lo), "=f"(hi) : "l"(v));
    return lo + hi;
}

// ------------------------------------------------------------------
// histogram + g_item init + R transpose (all independent prep work)
__global__ __launch_bounds__(256)
void k_count(const int* __restrict__ mem_r,
             const int* __restrict__ items,
             const float* __restrict__ entity,
             const float* __restrict__ rel, int B)
{
    __shared__ int hist[NREL];
    const int hop   = blockIdx.y;
    const int total = B * NMEM;
    const int chunk = (total + CBLK - 1) / CBLK;
    const int start = blockIdx.x * chunk;

    for (int i = threadIdx.x; i < NREL; i += 256) hist[i] = 0;
    __syncthreads();

    const int* src = mem_r + hop * total;
    {
        int base = start + threadIdx.x * 8;
        if (base + 8 <= start + chunk && start + chunk <= total) {
            int4 v0 = *(const int4*)(src + base);
            int4 v1 = *(const int4*)(src + base + 4);
            atomicAdd(&hist[v0.x], 1); atomicAdd(&hist[v0.y], 1);
            atomicAdd(&hist[v0.z], 1); atomicAdd(&hist[v0.w], 1);
            atomicAdd(&hist[v1.x], 1); atomicAdd(&hist[v1.y], 1);
            atomicAdd(&hist[v1.z], 1); atomicAdd(&hist[v1.w], 1);
        } else {
            for (int k = threadIdx.x * 8; k < threadIdx.x * 8 + 8; ++k)
                if (k < chunk && start + k < total)
                    atomicAdd(&hist[src[start + k]], 1);
        }
    }

    const int nthr = CBLK * NHOP * 256;
    const int gid  = (blockIdx.y * CBLK + blockIdx.x) * 256 + threadIdx.x;

    // g_item[b] = entity[items[b]]
    {
        const int nvec = B * (D / 4);          // float4 count
        for (int i = gid; i < nvec; i += nthr) {
            int b = i >> 4, c = i & 15;
            ((float4*)g_item)[i] =
                ((const float4*)(entity + (size_t)items[b] * D))[c];
        }
    }
    // g_RT[r][j*64+i] = rel[r*4096 + i*64 + j]  (coalesced writes)
    {
        const int nelem = NREL * D * D;
        for (int w = gid; w < nelem; w += nthr) {
            int r = w >> 12, j = (w >> 6) & 63, i = w & 63;
            ((float*)g_RT)[w] = rel[(r << 12) + (i << 6) + j];
        }
    }
    __syncthreads();

    for (int i = threadIdx.x; i < NREL; i += 256)
        g_parthist[hop][blockIdx.x][i] = hist[i];
}

__global__ __launch_bounds__(512)
void k_scan(const float* __restrict__ W)
{
    __shared__ int cnt[NHOP][NREL];
    const int tid = threadIdx.x;
    if (tid < NHOP * NREL) {
        int hop = tid / NREL, r = tid - hop * NREL;
        int s = 0;
        #pragma unroll 8
        for (int b = 0; b < CBLK; ++b) s += g_parthist[hop][b][r];
        cnt[hop][r] = s;
        g_cursor[hop][r] = 0;
    }
    for (int idx = tid; idx < D * D; idx += 512)
        g_Wt[(idx & (D - 1)) * D + (idx >> 6)] = W[idx];
    __syncthreads();
    if (tid < NHOP) {
        int acc = 0;
        for (int r = 0; r < NREL; ++r) { g_off[tid][r] = acc; acc += cnt[tid][r]; }
        g_off[tid][NREL] = acc;
    }
}

__global__ __launch_bounds__(256)
void k_scatter(const int* __restrict__ mem_r, int B)
{
    __shared__ int hist[NREL];
    __shared__ int base_s[NREL];
    const int hop   = blockIdx.y;
    const int total = B * NMEM;
    const int chunk = (total + CBLK - 1) / CBLK;
    const int start = blockIdx.x * chunk;

    for (int i = threadIdx.x; i < NREL; i += 256) hist[i] = 0;
    __syncthreads();

    const int* src = mem_r + hop * total;
    int rr[8], lrank[8], idx0 = start + threadIdx.x * 8;
    bool vec = ((chunk & 7) == 0) && (idx0 + 8 <= start + chunk) &&
               (start + chunk <= total);
    if (vec) {
        int4 v0 = *(const int4*)(src + idx0);
        int4 v1 = *(const int4*)(src + idx0 + 4);
        rr[0]=v0.x; rr[1]=v0.y; rr[2]=v0.z; rr[3]=v0.w;
        rr[4]=v1.x; rr[5]=v1.y; rr[6]=v1.z; rr[7]=v1.w;
        #pragma unroll
        for (int t = 0; t < 8; ++t) lrank[t] = atomicAdd(&hist[rr[t]], 1);
    } else {
        #pragma unroll
        for (int t = 0; t < 8; ++t) {
            int k = threadIdx.x * 8 + t;
            rr[t] = -1;
            if (k < chunk && start + k < total) {
                rr[t]    = src[start + k];
                lrank[t] = atomicAdd(&hist[rr[t]], 1);
            }
        }
    }
    __syncthreads();

    for (int i = threadIdx.x; i < NREL; i += 256) {
        int c = hist[i];
        base_s[i] = g_off[hop][i] + (c ? atomicAdd(&g_cursor[hop][i], c) : 0);
    }
    __syncthreads();

    #pragma unroll
    for (int t = 0; t < 8; ++t)
        if (vec || rr[t] >= 0)
            g_slots[hop][base_s[rr[t]] + lrank[t]] = idx0 + t;
}

// ------------------------------------------------------------------
// GEMM for BOTH hops in one launch, grid (NREL, YSPLIT, NHOP).
// hop 0: fused logit dot vs initial g_item -> g_logits0 (1 float/slot)
// hop 1: store Y rows -> g_Y1 (consumed by k_upd1 after item update)
__global__ __launch_bounds__(128, 5)
void k_gemm(const int* __restrict__ mem_h,
            const float* __restrict__ entity,
            int B)
{
    const int hop  = blockIdx.z;
    const int r    = blockIdx.x;
    const int base = g_off[hop][r];
    const int n    = g_off[hop][r + 1] - base;
    const int ntiles = (n + TM - 1) / TM;
    if ((int)blockIdx.y >= ntiles) return;

    extern __shared__ char smem[];
    const uint32_t rbase = smem_u32(smem + ROFF);
    const uint32_t hbase = smem_u32(smem + HOFF);
    int* sslot = (int*)(smem + SOFF);

    const int tid  = threadIdx.x;
    const int ts   = tid >> 3;      // 0..15
    const int ti   = tid & 7;       // 0..7

    const int* __restrict__ mh = mem_h + (size_t)hop * B * NMEM;

    bool first = true;
    for (int t = blockIdx.y; t < ntiles; t += YSPLIT) {
        if (!first) __syncthreads();   // previous compute done before overwrite

        // gather tile t into H (in-row 16B skew)
        {
            int s = t * TM + tid;
            if (tid < TM) {
                int slot = (s < n) ? g_slots[hop][base + s] : -1;
                sslot[tid] = slot;
                if (slot >= 0) {
                    const char* src = (const char*)(entity + (size_t)mh[slot] * D);
                    uint32_t rowbase = hbase + tid * HROWB;
                    const uint32_t sk = (tid & 7) * 16;
                    #pragma unroll
                    for (int c = 0; c < 16; ++c)
                        cp16(rowbase + ((sk + c * 16) & 255), src + c * 16);
                }
            }
            cp_commit();
        }

        if (first) {
            // contiguous async copy of pre-transposed R (no STS transpose)
            const char* Rp = (const char*)&g_RT[r][0];
            #pragma unroll
            for (int c = 0; c < 8; ++c)
                cp16(rbase + tid * 128 + c * 16, Rp + tid * 128 + c * 16);
            cp_commit();
            first = false;
        }

        cp_wait<0>();
        __syncthreads();

        const float4* R4 = (const float4*)(smem + ROFF);  // [j][i/4], j rows of 16
        const float4* H4 = (const float4*)(smem + HOFF);

        unsigned long long acc2[KS][4];
        #pragma unroll
        for (int k = 0; k < KS; ++k)
            #pragma unroll
            for (int p = 0; p < 4; ++p) acc2[k][p] = 0ull;

        #pragma unroll 2
        for (int jq = 0; jq < 16; ++jq) {
            float af[KS][4];
            #pragma unroll
            for (int k = 0; k < KS; ++k) {
                float4 a = H4[(ts + 16 * k) * 16 + (((ts & 7) + jq) & 15)];
                af[k][0] = a.x; af[k][1] = a.y; af[k][2] = a.z; af[k][3] = a.w;
            }
            #pragma unroll
            for (int jj = 0; jj < 4; ++jj) {
                const ulonglong2* bp =
                    (const ulonglong2*)(R4 + (4 * jq + jj) * 16 + ti * 2);
                ulonglong2 t0 = bp[0], t1 = bp[1];
                unsigned long long b2[4] = {t0.x, t0.y, t1.x, t1.y};
                #pragma unroll
                for (int k = 0; k < KS; ++k) {
                    unsigned long long av2 = pack2(af[k][jj]);
                    #pragma unroll
                    for (int p = 0; p < 4; ++p)
                        fma2(acc2[k][p], av2, b2[p]);
                }
            }
        }

        if (hop == 0) {
            // fused: logit = acc . item_b (initial items), 8-lane reduce
            #pragma unroll
            for (int k = 0; k < KS; ++k) {
                int slot = sslot[ts + 16 * k];
                float dot = 0.0f;
                if (slot >= 0) {
                    const ulonglong2* iv =
                        (const ulonglong2*)&g_item[slot >> 4][ti * 8];
                    ulonglong2 q0 = iv[0], q1 = iv[1];
                    unsigned long long d2 = 0ull;
                    fma2(d2, acc2[k][0], q0.x);
                    fma2(d2, acc2[k][1], q0.y);
                    fma2(d2, acc2[k][2], q1.x);
                    fma2(d2, acc2[k][3], q1.y);
                    dot = hsum2(d2);
                }
                dot += __shfl_xor_sync(0xffffffffu, dot, 1);
                dot += __shfl_xor_sync(0xffffffffu, dot, 2);
                dot += __shfl_xor_sync(0xffffffffu, dot, 4);
                if (ti == 0 && slot >= 0) g_logits0[slot] = dot;
            }
        } else {
            #pragma unroll
            for (int k = 0; k < KS; ++k) {
                int slot = sslot[ts + 16 * k];
                if (slot >= 0) {
                    ulonglong2* dst = (ulonglong2*)&g_Y1[slot][ti * 8];
                    ulonglong2 v0, v1;
                    v0.x = acc2[k][0]; v0.y = acc2[k][1];
                    v1.x = acc2[k][2]; v1.y = acc2[k][3];
                    dst[0] = v0;
                    dst[1] = v1;
                }
            }
        }
    }
}

// ------------------------------------------------------------------
// hop-0 epilogue: softmax(g_logits0), o, y, item1 = Wt@(item+o).
// 2 batch elements per 128-thread block.
__global__ __launch_bounds__(128)
void k_upd0(const int* __restrict__ mem_t,
            const float* __restrict__ entity, int B)
{
    const int tid  = threadIdx.x;
    const int sub  = tid >> 6;
    const int t    = tid & 63;
    const int b    = blockIdx.x * 2 + sub;

    __shared__ float lgs[2][NMEM];
    __shared__ float probs[2][NMEM];
    __shared__ float vbuf[2][D];

    float item = g_item[b][t];

    if (t < NMEM) {
        float lg = g_logits0[b * NMEM + t];
        lgs[sub][t] = lg;
    }
    __syncthreads();
    if (t < NMEM) {
        float mx = lgs[sub][0];
        #pragma unroll
        for (int k = 1; k < NMEM; ++k) mx = fmaxf(mx, lgs[sub][k]);
        probs[sub][t] = expf(lgs[sub][t] - mx);
    }
    __syncthreads();

    float denom = 0.0f;
    #pragma unroll
    for (int m = 0; m < NMEM; ++m) denom += probs[sub][m];

    const int* tp = mem_t + b * NMEM;   // hop 0
    float o = 0.0f;
    #pragma unroll
    for (int m = 0; m < NMEM; ++m)
        o = fmaf(probs[sub][m], entity[(size_t)tp[m] * D + t], o);
    o /= denom;

    g_y[b][t] = o;
    vbuf[sub][t] = item + o;
    __syncthreads();

    float acc = 0.0f;
    #pragma unroll 8
    for (int j = 0; j < D; ++j)
        acc = fmaf(g_Wt[j * D + t], vbuf[sub][j], acc);
    g_item[b][t] = acc;
}

// ------------------------------------------------------------------
// hop-1 epilogue: logits = Y1 . item1, softmax, o, y += o,
// item2 = Wt@(item1+o), score = dot(item2, y).
__global__ __launch_bounds__(128)
void k_upd1(const int* __restrict__ mem_t,
            const float* __restrict__ entity,
            float* __restrict__ out, int B)
{
    const int tid  = threadIdx.x;
    const int sub  = tid >> 6;
    const int t    = tid & 63;
    const int lane = tid & 31;
    const int warp = tid >> 5;
    const int wH   = warp & 1;
    const int b    = blockIdx.x * 2 + sub;

    __shared__ float item_sv[2][D];
    __shared__ float vbuf[2][D];
    __shared__ float lgs[2][NMEM];
    __shared__ float probs[2][NMEM];
    __shared__ float red[4];

    float item = g_item[b][t];
    item_sv[sub][t] = item;
    __syncthreads();

    #pragma unroll
    for (int s = 0; s < 8; ++s) {
        int m = wH * 8 + s;
        const float* Yp = g_Y1[b * NMEM + m];
        float v = Yp[lane] * item_sv[sub][lane] +
                  Yp[lane + 32] * item_sv[sub][lane + 32];
        #pragma unroll
        for (int off = 16; off > 0; off >>= 1)
            v += __shfl_xor_sync(0xffffffffu, v, off);
        if (lane == 0) lgs[sub][m] = v;
    }
    __syncthreads();

    if (t < NMEM) {
        float mx = lgs[sub][0];
        #pragma unroll
        for (int k = 1; k < NMEM; ++k) mx = fmaxf(mx, lgs[sub][k]);
        probs[sub][t] = expf(lgs[sub][t] - mx);
    }
    __syncthreads();

    float denom = 0.0f;
    #pragma unroll
    for (int m = 0; m < NMEM; ++m) denom += probs[sub][m];

    const int* tp = mem_t + (size_t)B * NMEM + b * NMEM;   // hop 1
    float o = 0.0f;
    #pragma unroll
    for (int m = 0; m < NMEM; ++m)
        o = fmaf(probs[sub][m], entity[(size_t)tp[m] * D + t], o);
    o /= denom;

    float y = g_y[b][t] + o;
    vbuf[sub][t] = item + o;
    __syncthreads();

    float acc = 0.0f;
    #pragma unroll 8
    for (int j = 0; j < D; ++j)
        acc = fmaf(g_Wt[j * D + t], vbuf[sub][j], acc);

    float p = acc * y;
    #pragma unroll
    for (int off = 16; off > 0; off >>= 1)
        p += __shfl_xor_sync(0xffffffffu, p, off);
    if (lane == 0) red[warp] = p;
    __syncthreads();
    if (tid == 0)  out[b] = red[0] + red[1];
    if (tid == 64) out[b] = red[2] + red[3];
}

// ------------------------------------------------------------------
extern "C" void kernel_launch(void* const* d_in, const int* in_sizes, int n_in,
                              void* d_out, int out_size)
{
    const int*   items  = (const int*)  d_in[0];
    const int*   mem_h  = (const int*)  d_in[1];
    const int*   mem_r  = (const int*)  d_in[2];
    const int*   mem_t  = (const int*)  d_in[3];
    const float* entity = (const float*)d_in[4];
    const float* rel    = (const float*)d_in[5];
    const float* W      = (const float*)d_in[6];
    float*       out    = (float*)d_out;

    const int B = in_sizes[0];   // 4096

    static bool attr_set = false;
    if (!attr_set) {
        cudaFuncSetAttribute(k_gemm, cudaFuncAttributeMaxDynamicSharedMemorySize,
                             GEMM_SMEM);
        attr_set = true;
    }

    k_count  <<<dim3(CBLK, NHOP), 256>>>(mem_r, items, entity, rel, B);
    k_scan   <<<1, 512>>>(W);
    k_scatter<<<dim3(CBLK, NHOP), 256>>>(mem_r, B);
    k_gemm   <<<dim3(NREL, YSPLIT, NHOP), 128, GEMM_SMEM>>>(mem_h, entity, B);
    k_upd0   <<<B / 2, 128>>>(mem_t, entity, B);
    k_upd1   <<<B / 2, 128>>>(mem_t, entity, out, B);
}